// round 2
// baseline (speedup 1.0000x reference)
#include <cuda_runtime.h>
#include <cstdint>
#include <cstddef>

#define BB 64
#define TT 2048
#define DD 256
#define HH 512
#define GCN 2048   /* 4*HH gate columns: [j|i|f|o] */
#define RBLOCKS 128

// ---------------- scratch (device globals: allocation-free rule) ----------------
__device__ float g_xproj[(size_t)TT * GCN * BB];   // [t][gc][b]  (1 GiB)
__device__ float g_hs[(size_t)TT * BB * HH];       // [t][b][h]   (256 MiB)
__device__ unsigned g_bar_gen;
__device__ unsigned g_bar_cnt;

__device__ __forceinline__ float fsigmoid_(float x) {
    return 1.0f / (1.0f + __expf(-x));
}
__device__ __forceinline__ float ftanh_(float x) {
    float e = __expf(2.0f * x);
    return 1.0f - 2.0f / (e + 1.0f);
}

// ---- cp.async helpers ----
__device__ __forceinline__ void cp16(void* dst_smem, const void* src_gmem) {
    unsigned d = (unsigned)__cvta_generic_to_shared(dst_smem);
    asm volatile("cp.async.cg.shared.global [%0], [%1], 16;\n" :: "r"(d), "l"(src_gmem));
}
__device__ __forceinline__ void cp_commit() {
    asm volatile("cp.async.commit_group;\n");
}
template <int N> __device__ __forceinline__ void cp_wait() {
    asm volatile("cp.async.wait_group %0;\n" :: "n"(N));
}

// =====================================================================
// Kernel 1: input projections (double-buffered SGEMM)
// block: tile [128 gc] x [64 b] at one t. K=256 in 8 chunks of 32.
// =====================================================================
__global__ void __launch_bounds__(256) proj_kernel(
    const float* __restrict__ x,
    const float* __restrict__ Wj, const float* __restrict__ Wi,
    const float* __restrict__ Wf, const float* __restrict__ Wo,
    const float* __restrict__ bj, const float* __restrict__ bi,
    const float* __restrict__ bf, const float* __restrict__ bo)
{
    extern __shared__ float sm[];
    float* Wsm = sm;                 // [2][32 kk][128 gc]
    float* Xsm = sm + 2 * 32 * 128;  // [2][64 b][40]   (k pad to 40 for 16B-aligned rows)

    const int t   = blockIdx.y;
    const int gc0 = blockIdx.x * 128;
    const int g   = gc0 >> 9;
    const int hq0 = gc0 & 511;
    const float* W  = (g == 0) ? Wj : (g == 1) ? Wi : (g == 2) ? Wf : Wo;
    const float* bv = (g == 0) ? bj : (g == 1) ? bi : (g == 2) ? bf : bo;
    const int tid = threadIdx.x;
    const int tb = tid >> 4;    // 0..15 -> 4 batches
    const int tc = tid & 15;    // 0..15 -> cols {i4*64 + tc*4 + q}

    float acc[4][8];
#pragma unroll
    for (int j = 0; j < 4; j++)
#pragma unroll
        for (int i = 0; i < 8; i++) acc[j][i] = 0.0f;

    auto prefetch = [&](int kc, int buf) {
        const float* Wp = W + (size_t)(kc * 32) * HH + hq0;
        float* wd = Wsm + buf * (32 * 128);
#pragma unroll
        for (int r = 0; r < 4; r++) {
            int idx = r * 256 + tid;         // 0..1023
            int kk = idx >> 5, c4 = idx & 31;
            cp16(wd + kk * 128 + c4 * 4, Wp + (size_t)kk * HH + c4 * 4);
        }
        float* xd = Xsm + buf * (64 * 40);
#pragma unroll
        for (int r = 0; r < 2; r++) {
            int idx = r * 256 + tid;         // 0..511
            int bb = idx >> 3, k4 = idx & 7;
            cp16(xd + bb * 40 + k4 * 4,
                 x + ((size_t)bb * TT + t) * DD + kc * 32 + k4 * 4);
        }
    };

    prefetch(0, 0);
    cp_commit();

    for (int kc = 0; kc < 8; kc++) {
        int buf = kc & 1;
        if (kc < 7) prefetch(kc + 1, buf ^ 1);
        cp_commit();
        cp_wait<1>();
        __syncthreads();

        const float4* Wb4 = (const float4*)(Wsm + buf * (32 * 128));
        const float*  Xb  = Xsm + buf * (64 * 40);
#pragma unroll
        for (int kk = 0; kk < 32; kk++) {
            float4 wv0 = Wb4[kk * 32 + tc];
            float4 wv1 = Wb4[kk * 32 + 16 + tc];
            float xv[4];
#pragma unroll
            for (int j = 0; j < 4; j++) xv[j] = Xb[(tb * 4 + j) * 40 + kk];
#pragma unroll
            for (int j = 0; j < 4; j++) {
                acc[j][0] = fmaf(xv[j], wv0.x, acc[j][0]);
                acc[j][1] = fmaf(xv[j], wv0.y, acc[j][1]);
                acc[j][2] = fmaf(xv[j], wv0.z, acc[j][2]);
                acc[j][3] = fmaf(xv[j], wv0.w, acc[j][3]);
                acc[j][4] = fmaf(xv[j], wv1.x, acc[j][4]);
                acc[j][5] = fmaf(xv[j], wv1.y, acc[j][5]);
                acc[j][6] = fmaf(xv[j], wv1.z, acc[j][6]);
                acc[j][7] = fmaf(xv[j], wv1.w, acc[j][7]);
            }
        }
        __syncthreads();
    }

    // epilogue: xproj[t][gc0+c][b], c = i4*64 + tc*4 + q
#pragma unroll
    for (int i4 = 0; i4 < 2; i4++) {
#pragma unroll
        for (int q = 0; q < 4; q++) {
            int c = i4 * 64 + tc * 4 + q;
            float bb = bv[hq0 + c];
            float4 v = make_float4(acc[0][i4 * 4 + q] + bb, acc[1][i4 * 4 + q] + bb,
                                   acc[2][i4 * 4 + q] + bb, acc[3][i4 * 4 + q] + bb);
            *(float4*)(g_xproj + ((size_t)t * GCN + gc0 + c) * BB + tb * 4) = v;
        }
    }
}

// =====================================================================
// Kernel 2: persistent recurrence. 128 blocks x 256 threads.
// Warp = (hq-lane l, batch-half). Each lane computes ALL 4 gates for
// (b, hq_base+l): c stays in a register, no cross-warp gate exchange.
// h_{t-1} staged via 4-chunk cp.async pipeline overlapped with FFMA.
// =====================================================================
__global__ void __launch_bounds__(256) recur_kernel(
    const float* __restrict__ h0in, const float* __restrict__ c0in,
    const float* __restrict__ Uj, const float* __restrict__ Ui,
    const float* __restrict__ Uf, const float* __restrict__ Uo,
    float* __restrict__ dout)
{
    extern __shared__ float sm[];
    float* h_smf = sm;               // [64 b][512 k] floats, xor-swizzled float4
    float* U_sm  = sm + 64 * 512;    // [4 l][512 hk][4 g]

    const int tid = threadIdx.x;
    const int hq_base = blockIdx.x * 4;

    // U load: U_sm[((l*512)+hk)*4 + g] = U_g[hk][hq_base+l]
    for (int idx = tid; idx < 512 * 16; idx += 256) {
        int g = idx & 3, hk = (idx >> 2) & 511, l = idx >> 11;
        const float* Up = (g == 0) ? Uj : (g == 1) ? Ui : (g == 2) ? Uf : Uo;
        U_sm[idx] = Up[(size_t)hk * HH + hq_base + l];
    }
    __syncthreads();

    const int wid  = tid >> 5;
    const int lane = tid & 31;
    const int l    = wid >> 1;
    const int bh   = wid & 1;
    const int b    = bh * 32 + lane;
    const int xm   = b & 7;
    const int hq   = hq_base + l;

    float4* h4 = (float4*)h_smf;
    const float4* U4 = (const float4*)U_sm;   // U4[l*512 + hk] = (j,i,f,o)

    float c = c0in[(size_t)b * HH + hq];
    float hval = 0.0f;

    for (int t = 0; t < TT; t++) {
        // ---- issue all 4 h-chunks (cp.async), one commit group per chunk ----
        const float4* src = (t == 0) ? (const float4*)h0in
                                     : (const float4*)(g_hs + (size_t)(t - 1) * BB * HH);
#pragma unroll
        for (int ch = 0; ch < 4; ch++) {
#pragma unroll
            for (int r = 0; r < 8; r++) {
                int e = r * 256 + tid;          // 0..2047
                int bb = e >> 5, kk = e & 31;
                int k4 = ch * 32 + kk;
                cp16(&h4[bb * 128 + (k4 ^ (bb & 7))], &src[bb * 128 + k4]);
            }
            cp_commit();
        }

        // ---- xproj prefetch (independent of h) ----
        const float* xp = g_xproj + (size_t)t * GCN * BB;
        float aj = xp[((size_t)0 * HH + hq) * BB + b];
        float ai = xp[((size_t)1 * HH + hq) * BB + b];
        float af = xp[((size_t)2 * HH + hq) * BB + b];
        float ao = xp[((size_t)3 * HH + hq) * BB + b];

        // ---- 4 chunks: wait, sync, FFMA over 32 k4 each ----
#define RECUR_CHUNK(CH, WN)                                                    \
        {                                                                      \
            cp_wait<WN>();                                                     \
            __syncthreads();                                                   \
            _Pragma("unroll 4")                                                \
            for (int kk = 0; kk < 32; kk++) {                                  \
                int k4 = CH * 32 + kk;                                         \
                float4 hv = h4[b * 128 + (k4 ^ xm)];                           \
                const float4* Uc = U4 + ((l << 9) | (k4 << 2));                \
                float4 u0 = Uc[0], u1 = Uc[1], u2 = Uc[2], u3 = Uc[3];         \
                aj = fmaf(hv.x, u0.x, aj); ai = fmaf(hv.x, u0.y, ai);          \
                af = fmaf(hv.x, u0.z, af); ao = fmaf(hv.x, u0.w, ao);          \
                aj = fmaf(hv.y, u1.x, aj); ai = fmaf(hv.y, u1.y, ai);          \
                af = fmaf(hv.y, u1.z, af); ao = fmaf(hv.y, u1.w, ao);          \
                aj = fmaf(hv.z, u2.x, aj); ai = fmaf(hv.z, u2.y, ai);          \
                af = fmaf(hv.z, u2.z, af); ao = fmaf(hv.z, u2.w, ao);          \
                aj = fmaf(hv.w, u3.x, aj); ai = fmaf(hv.w, u3.y, ai);          \
                af = fmaf(hv.w, u3.z, af); ao = fmaf(hv.w, u3.w, ao);          \
            }                                                                  \
        }
        RECUR_CHUNK(0, 3)
        RECUR_CHUNK(1, 2)
        RECUR_CHUNK(2, 1)
        RECUR_CHUNK(3, 0)
#undef RECUR_CHUNK

        // ---- gates: j,i,o sigmoid; f tanh (module default quirk) ----
        aj = fsigmoid_(aj); ai = fsigmoid_(ai); ao = fsigmoid_(ao);
        af = ftanh_(af);
        c = fmaf(af, c, ai * aj);
        hval = ao * ftanh_(c);
        g_hs[((size_t)t * BB + b) * HH + hq] = hval;

        // ---- grid barrier (all 128 blocks co-resident: 1 block/SM) ----
        __syncthreads();
        if (tid == 0) {
            __threadfence();
            unsigned myg = *(volatile unsigned*)&g_bar_gen;
            if (atomicAdd(&g_bar_cnt, 1u) == RBLOCKS - 1) {
                g_bar_cnt = 0;
                __threadfence();
                *(volatile unsigned*)&g_bar_gen = myg + 1u;
            } else {
                while (*(volatile unsigned*)&g_bar_gen == myg) { __nanosleep(32); }
            }
            __threadfence();
        }
        __syncthreads();
    }

    // ---- epilogue: h_last, c_last (both live in registers) ----
    {
        size_t OH = (size_t)BB * TT * DD;
        dout[OH + (size_t)b * HH + hq] = hval;
        dout[OH + (size_t)BB * HH + (size_t)b * HH + hq] = c;
    }
}

// =====================================================================
// Kernel 3: y[b][t][d] = sum_h hs[t][b][h] * Wy[h][d] + by[d]
// One block per t; [64 b]x[256 d] tile; K=512 in 16 chunks of 32,
// double-buffered via cp.async.
// =====================================================================
__global__ void __launch_bounds__(256, 2) ygemm_kernel(
    const float* __restrict__ Wy, const float* __restrict__ by,
    float* __restrict__ y)
{
    extern __shared__ float sm[];
    float* Wsm = sm;                 // [2][32 kk][256 d]
    float* Hsm = sm + 2 * 32 * 256;  // [2][64 b][40]

    const int t = blockIdx.x;
    const int tid = threadIdx.x;
    const int tb = tid >> 4;   // 4 batches
    const int tc = tid & 15;   // d = i4*64 + tc*4 + q

    float acc[4][16];
#pragma unroll
    for (int j = 0; j < 4; j++)
#pragma unroll
        for (int i = 0; i < 16; i++) acc[j][i] = 0.0f;

    auto prefetch = [&](int kc, int buf) {
        float* wd = Wsm + buf * (32 * 256);
#pragma unroll
        for (int r = 0; r < 8; r++) {
            int idx = r * 256 + tid;        // 0..2047
            int kk = idx >> 6, c4 = idx & 63;
            cp16(wd + kk * 256 + c4 * 4,
                 Wy + (size_t)(kc * 32 + kk) * DD + c4 * 4);
        }
        float* hd = Hsm + buf * (64 * 40);
#pragma unroll
        for (int r = 0; r < 2; r++) {
            int idx = r * 256 + tid;        // 0..511
            int bb = idx >> 3, k4 = idx & 7;
            cp16(hd + bb * 40 + k4 * 4,
                 g_hs + ((size_t)t * BB + bb) * HH + kc * 32 + k4 * 4);
        }
    };

    prefetch(0, 0);
    cp_commit();

    for (int kc = 0; kc < 16; kc++) {
        int buf = kc & 1;
        if (kc < 15) prefetch(kc + 1, buf ^ 1);
        cp_commit();
        cp_wait<1>();
        __syncthreads();

        const float4* Wb4 = (const float4*)(Wsm + buf * (32 * 256));
        const float*  Hb  = Hsm + buf * (64 * 40);
#pragma unroll 8
        for (int kk = 0; kk < 32; kk++) {
            float4 wv[4];
#pragma unroll
            for (int i4 = 0; i4 < 4; i4++) wv[i4] = Wb4[kk * 64 + i4 * 16 + tc];
            float xv[4];
#pragma unroll
            for (int j = 0; j < 4; j++) xv[j] = Hb[(tb * 4 + j) * 40 + kk];
#pragma unroll
            for (int j = 0; j < 4; j++)
#pragma unroll
                for (int i4 = 0; i4 < 4; i4++) {
                    acc[j][i4 * 4 + 0] = fmaf(xv[j], wv[i4].x, acc[j][i4 * 4 + 0]);
                    acc[j][i4 * 4 + 1] = fmaf(xv[j], wv[i4].y, acc[j][i4 * 4 + 1]);
                    acc[j][i4 * 4 + 2] = fmaf(xv[j], wv[i4].z, acc[j][i4 * 4 + 2]);
                    acc[j][i4 * 4 + 3] = fmaf(xv[j], wv[i4].w, acc[j][i4 * 4 + 3]);
                }
        }
        __syncthreads();
    }

#pragma unroll
    for (int j = 0; j < 4; j++) {
#pragma unroll
        for (int i4 = 0; i4 < 4; i4++) {
            int d = i4 * 64 + tc * 4;
            float4 v = make_float4(acc[j][i4 * 4 + 0] + by[d + 0],
                                   acc[j][i4 * 4 + 1] + by[d + 1],
                                   acc[j][i4 * 4 + 2] + by[d + 2],
                                   acc[j][i4 * 4 + 3] + by[d + 3]);
            *(float4*)(y + (((size_t)(tb * 4 + j)) * TT + t) * DD + d) = v;
        }
    }
}

// =====================================================================
extern "C" void kernel_launch(void* const* d_in, const int* in_sizes, int n_in,
                              void* d_out, int out_size)
{
    (void)in_sizes; (void)n_in; (void)out_size;
    const float* x  = (const float*)d_in[0];
    const float* h0 = (const float*)d_in[1];
    const float* c0 = (const float*)d_in[2];
    const float* Wj = (const float*)d_in[3];
    const float* Wi = (const float*)d_in[4];
    const float* Wf = (const float*)d_in[5];
    const float* Wo = (const float*)d_in[6];
    const float* Uj = (const float*)d_in[7];
    const float* Ui = (const float*)d_in[8];
    const float* Uf = (const float*)d_in[9];
    const float* Uo = (const float*)d_in[10];
    const float* bj = (const float*)d_in[11];
    const float* bi = (const float*)d_in[12];
    const float* bf = (const float*)d_in[13];
    const float* bo = (const float*)d_in[14];
    const float* Wy = (const float*)d_in[15];
    const float* by = (const float*)d_in[16];
    float* out = (float*)d_out;

    const size_t smem_proj = (size_t)(2 * 32 * 128 + 2 * 64 * 40) * 4;  // 53,248
    const size_t smem_rec  = (size_t)(64 * 512 + 512 * 16) * 4;         // 163,840
    const size_t smem_y    = (size_t)(2 * 32 * 256 + 2 * 64 * 40) * 4;  // 86,016

    cudaFuncSetAttribute(proj_kernel,  cudaFuncAttributeMaxDynamicSharedMemorySize, (int)smem_proj);
    cudaFuncSetAttribute(recur_kernel, cudaFuncAttributeMaxDynamicSharedMemorySize, (int)smem_rec);
    cudaFuncSetAttribute(ygemm_kernel, cudaFuncAttributeMaxDynamicSharedMemorySize, (int)smem_y);

    proj_kernel<<<dim3(16, TT), 256, smem_proj>>>(x, Wj, Wi, Wf, Wo, bj, bi, bf, bo);
    recur_kernel<<<RBLOCKS, 256, smem_rec>>>(h0, c0, Uj, Ui, Uf, Uo, out);
    ygemm_kernel<<<TT, 256, smem_y>>>(Wy, by, out);
}

// round 3
// speedup vs baseline: 1.3457x; 1.3457x over previous
#include <cuda_runtime.h>
#include <cstdint>
#include <cstddef>

#define BB 64
#define TT 2048
#define DD 256
#define HH 512
#define GCN 2048   /* 4*HH gate columns: [j|i|f|o] */
#define RBLOCKS 128

// ---------------- scratch (device globals: allocation-free rule) ----------------
__device__ float g_xproj[(size_t)TT * GCN * BB];   // [t][gc][b]  (1 GiB)
__device__ float g_hs[(size_t)TT * BB * HH];       // [t][b][h]   (256 MiB)
__device__ unsigned g_bar_gen;
__device__ unsigned g_bar_cnt;

__device__ __forceinline__ float fsigmoid_(float x) {
    return 1.0f / (1.0f + __expf(-x));
}
__device__ __forceinline__ float ftanh_(float x) {
    float e = __expf(2.0f * x);
    return 1.0f - 2.0f / (e + 1.0f);
}

// ---- packed f32x2 helpers (FFMA2 path: only reachable via PTX) ----
__device__ __forceinline__ unsigned long long pack2(float lo, float hi) {
    unsigned long long r;
    asm("mov.b64 %0, {%1, %2};" : "=l"(r)
        : "r"(__float_as_uint(lo)), "r"(__float_as_uint(hi)));
    return r;
}
__device__ __forceinline__ unsigned long long bcast2(float v) {
    unsigned long long r;
    asm("mov.b64 %0, {%1, %1};" : "=l"(r) : "r"(__float_as_uint(v)));
    return r;
}
__device__ __forceinline__ void fma2(unsigned long long& d,
                                     unsigned long long a, unsigned long long b) {
    asm("fma.rn.f32x2 %0, %1, %2, %0;" : "+l"(d) : "l"(a), "l"(b));
}
__device__ __forceinline__ void add2(unsigned long long& d, unsigned long long a) {
    asm("add.rn.f32x2 %0, %0, %1;" : "+l"(d) : "l"(a));
}
__device__ __forceinline__ float2 unpack2(unsigned long long v) {
    unsigned lo, hi;
    asm("mov.b64 {%0, %1}, %2;" : "=r"(lo), "=r"(hi) : "l"(v));
    return make_float2(__uint_as_float(lo), __uint_as_float(hi));
}

// ---- cp.async helpers ----
__device__ __forceinline__ void cp16(void* dst_smem, const void* src_gmem) {
    unsigned d = (unsigned)__cvta_generic_to_shared(dst_smem);
    asm volatile("cp.async.cg.shared.global [%0], [%1], 16;\n" :: "r"(d), "l"(src_gmem));
}
__device__ __forceinline__ void cp_commit() {
    asm volatile("cp.async.commit_group;\n");
}
template <int N> __device__ __forceinline__ void cp_wait() {
    asm volatile("cp.async.wait_group %0;\n" :: "n"(N));
}

// =====================================================================
// Kernel 1: input projections (double-buffered SGEMM, f32x2 math)
// block: tile [128 gc] x [64 b] at one t. K=256 in 8 chunks of 32.
// =====================================================================
__global__ void __launch_bounds__(256) proj_kernel(
    const float* __restrict__ x,
    const float* __restrict__ Wj, const float* __restrict__ Wi,
    const float* __restrict__ Wf, const float* __restrict__ Wo,
    const float* __restrict__ bj, const float* __restrict__ bi,
    const float* __restrict__ bf, const float* __restrict__ bo)
{
    extern __shared__ float sm[];
    float* Wsm = sm;                 // [2][32 kk][128 gc]
    float* Xsm = sm + 2 * 32 * 128;  // [2][64 b][40]

    const int t   = blockIdx.y;
    const int gc0 = blockIdx.x * 128;
    const int g   = gc0 >> 9;
    const int hq0 = gc0 & 511;
    const float* W  = (g == 0) ? Wj : (g == 1) ? Wi : (g == 2) ? Wf : Wo;
    const float* bv = (g == 0) ? bj : (g == 1) ? bi : (g == 2) ? bf : bo;
    const int tid = threadIdx.x;
    const int tb = tid >> 4;    // 0..15 -> 4 batches
    const int tc = tid & 15;    // cols {i4*64 + tc*4 + q}

    unsigned long long A[4][4];  // [j][pair]: pairs (0,1)(2,3)(4,5)(6,7) of acc[j][8]
#pragma unroll
    for (int j = 0; j < 4; j++)
#pragma unroll
        for (int p = 0; p < 4; p++) A[j][p] = 0ull;

    auto prefetch = [&](int kc, int buf) {
        const float* Wp = W + (size_t)(kc * 32) * HH + hq0;
        float* wd = Wsm + buf * (32 * 128);
#pragma unroll
        for (int r = 0; r < 4; r++) {
            int idx = r * 256 + tid;
            int kk = idx >> 5, c4 = idx & 31;
            cp16(wd + kk * 128 + c4 * 4, Wp + (size_t)kk * HH + c4 * 4);
        }
        float* xd = Xsm + buf * (64 * 40);
#pragma unroll
        for (int r = 0; r < 2; r++) {
            int idx = r * 256 + tid;
            int bb = idx >> 3, k4 = idx & 7;
            cp16(xd + bb * 40 + k4 * 4,
                 x + ((size_t)bb * TT + t) * DD + kc * 32 + k4 * 4);
        }
    };

    prefetch(0, 0);
    cp_commit();

    for (int kc = 0; kc < 8; kc++) {
        int buf = kc & 1;
        if (kc < 7) prefetch(kc + 1, buf ^ 1);
        cp_commit();
        cp_wait<1>();
        __syncthreads();

        const float4* Wb4 = (const float4*)(Wsm + buf * (32 * 128));
        const float*  Xb  = Xsm + buf * (64 * 40);
#pragma unroll
        for (int kk4 = 0; kk4 < 8; kk4++) {
            float4 xq[4];
#pragma unroll
            for (int j = 0; j < 4; j++)
                xq[j] = *(const float4*)(Xb + (tb * 4 + j) * 40 + kk4 * 4);
#pragma unroll
            for (int q = 0; q < 4; q++) {
                int kk = kk4 * 4 + q;
                ulonglong2 w0 = *(const ulonglong2*)(Wb4 + kk * 32 + tc);
                ulonglong2 w1 = *(const ulonglong2*)(Wb4 + kk * 32 + 16 + tc);
#pragma unroll
                for (int j = 0; j < 4; j++) {
                    float xs = ((const float*)&xq[j])[q];
                    unsigned long long hj = bcast2(xs);
                    fma2(A[j][0], hj, w0.x);
                    fma2(A[j][1], hj, w0.y);
                    fma2(A[j][2], hj, w1.x);
                    fma2(A[j][3], hj, w1.y);
                }
            }
        }
        __syncthreads();
    }

    // unpack + epilogue: xproj[t][gc0+c][b]
    float acc[4][8];
#pragma unroll
    for (int j = 0; j < 4; j++)
#pragma unroll
        for (int p = 0; p < 4; p++) {
            float2 v = unpack2(A[j][p]);
            acc[j][p * 2 + 0] = v.x;
            acc[j][p * 2 + 1] = v.y;
        }
#pragma unroll
    for (int i4 = 0; i4 < 2; i4++) {
#pragma unroll
        for (int q = 0; q < 4; q++) {
            int c = i4 * 64 + tc * 4 + q;
            float bb = bv[hq0 + c];
            float4 v = make_float4(acc[0][i4 * 4 + q] + bb, acc[1][i4 * 4 + q] + bb,
                                   acc[2][i4 * 4 + q] + bb, acc[3][i4 * 4 + q] + bb);
            *(float4*)(g_xproj + ((size_t)t * GCN + gc0 + c) * BB + tb * 4) = v;
        }
    }
}

// =====================================================================
// Kernel 2: persistent recurrence. 128 blocks x 256 threads.
// Warp = (hq-lane l, batch-half). Lane computes ALL 4 gates for (b, hq):
// c in a register. Gates paired (j,i)/(f,o) for f32x2 FFMA2.
// Single-phase staging (LDG->STS), one __syncthreads (R1-proven shape).
// =====================================================================
__global__ void __launch_bounds__(256) recur_kernel(
    const float* __restrict__ h0in, const float* __restrict__ c0in,
    const float* __restrict__ Uj, const float* __restrict__ Ui,
    const float* __restrict__ Uf, const float* __restrict__ Uo,
    float* __restrict__ dout)
{
    extern __shared__ float sm[];
    float* h_smf = sm;               // [64 b][512 k], xor-swizzled float4
    float* U_sm  = sm + 64 * 512;    // [4 l][512 hk][4 g] = (j,i,f,o) per hk

    const int tid = threadIdx.x;
    const int hq_base = blockIdx.x * 4;

    for (int idx = tid; idx < 512 * 16; idx += 256) {
        int g = idx & 3, hk = (idx >> 2) & 511, l = idx >> 11;
        const float* Up = (g == 0) ? Uj : (g == 1) ? Ui : (g == 2) ? Uf : Uo;
        U_sm[idx] = Up[(size_t)hk * HH + hq_base + l];
    }
    __syncthreads();

    const int wid  = tid >> 5;
    const int lane = tid & 31;
    const int l    = wid >> 1;
    const int bh   = wid & 1;
    const int b    = bh * 32 + lane;
    const int xm   = b & 7;
    const int hq   = hq_base + l;

    float4* h4 = (float4*)h_smf;
    const float4* U4 = (const float4*)U_sm;

    float c = c0in[(size_t)b * HH + hq];
    float hval = 0.0f;

    for (int t = 0; t < TT; t++) {
        // ---- xproj prefetch first (DRAM latency hidden under staging) ----
        const float* xp = g_xproj + (size_t)t * GCN * BB;
        float pj = xp[((size_t)0 * HH + hq) * BB + b];
        float pi = xp[((size_t)1 * HH + hq) * BB + b];
        float pf = xp[((size_t)2 * HH + hq) * BB + b];
        float po = xp[((size_t)3 * HH + hq) * BB + b];

        // ---- stage h_{t-1} into swizzled smem (single phase) ----
        const float4* src = (t == 0) ? (const float4*)h0in
                                     : (const float4*)(g_hs + (size_t)(t - 1) * BB * HH);
#pragma unroll 8
        for (int r = 0; r < 32; r++) {
            int idx = r * 256 + tid;
            int bb = idx >> 7, k4 = idx & 127;
            h4[bb * 128 + (k4 ^ (bb & 7))] = src[idx];
        }
        __syncthreads();

        // ---- paired-gate dot products: 2 chains per pair to break RAW ----
        unsigned long long a_ji0 = pack2(pj, pi), a_fo0 = pack2(pf, po);
        unsigned long long a_ji1 = 0ull,          a_fo1 = 0ull;

        const ulonglong2* Ubase = (const ulonglong2*)(U4 + (l << 9));
#pragma unroll 4
        for (int k4 = 0; k4 < 128; k4++) {
            float4 hv = h4[b * 128 + (k4 ^ xm)];
            const ulonglong2* Uc = Ubase + (k4 << 2);
            ulonglong2 u0 = Uc[0], u1 = Uc[1], u2 = Uc[2], u3 = Uc[3];
            unsigned long long h0p = bcast2(hv.x);
            unsigned long long h1p = bcast2(hv.y);
            unsigned long long h2p = bcast2(hv.z);
            unsigned long long h3p = bcast2(hv.w);
            fma2(a_ji0, h0p, u0.x); fma2(a_fo0, h0p, u0.y);
            fma2(a_ji1, h1p, u1.x); fma2(a_fo1, h1p, u1.y);
            fma2(a_ji0, h2p, u2.x); fma2(a_fo0, h2p, u2.y);
            fma2(a_ji1, h3p, u3.x); fma2(a_fo1, h3p, u3.y);
        }
        add2(a_ji0, a_ji1);
        add2(a_fo0, a_fo1);
        float2 vji = unpack2(a_ji0);
        float2 vfo = unpack2(a_fo0);

        // gates: j,i,o sigmoid; f tanh (module default quirk)
        float aj = fsigmoid_(vji.x);
        float ai = fsigmoid_(vji.y);
        float af = ftanh_(vfo.x);
        float ao = fsigmoid_(vfo.y);
        c = fmaf(af, c, ai * aj);
        hval = ao * ftanh_(c);
        g_hs[((size_t)t * BB + b) * HH + hq] = hval;

        // ---- grid barrier ----
        __syncthreads();
        if (tid == 0) {
            __threadfence();
            unsigned myg = *(volatile unsigned*)&g_bar_gen;
            if (atomicAdd(&g_bar_cnt, 1u) == RBLOCKS - 1) {
                g_bar_cnt = 0;
                __threadfence();
                *(volatile unsigned*)&g_bar_gen = myg + 1u;
            } else {
                while (*(volatile unsigned*)&g_bar_gen == myg) { __nanosleep(32); }
            }
            __threadfence();
        }
        __syncthreads();
    }

    {
        size_t OH = (size_t)BB * TT * DD;
        dout[OH + (size_t)b * HH + hq] = hval;
        dout[OH + (size_t)BB * HH + (size_t)b * HH + hq] = c;
    }
}

// =====================================================================
// Kernel 3: y[b][t][d] = sum_h hs[t][b][h] * Wy[h][d] + by[d]
// 512 threads (no forced min-blocks -> no spills), f32x2 math,
// double-buffered cp.async, K=512 in 16 chunks of 32.
// =====================================================================
__global__ void __launch_bounds__(512) ygemm_kernel(
    const float* __restrict__ Wy, const float* __restrict__ by,
    float* __restrict__ y)
{
    extern __shared__ float sm[];
    float* Wsm = sm;                 // [2][32 kk][256 d]
    float* Hsm = sm + 2 * 32 * 256;  // [2][64 b][40]

    const int t = blockIdx.x;
    const int tid = threadIdx.x;
    const int tb = tid >> 5;   // 0..15 -> 4 batches (constant per warp)
    const int tc = tid & 31;   // d4 = i2*32 + tc

    unsigned long long A[4][4];  // [j][i2*2+pp]: pairs of 8 floats
#pragma unroll
    for (int j = 0; j < 4; j++)
#pragma unroll
        for (int p = 0; p < 4; p++) A[j][p] = 0ull;

    auto prefetch = [&](int kc, int buf) {
        float* wd = Wsm + buf * (32 * 256);
#pragma unroll
        for (int r = 0; r < 4; r++) {
            int idx = r * 512 + tid;        // 0..2047
            int kk = idx >> 6, c4 = idx & 63;
            cp16(wd + kk * 256 + c4 * 4,
                 Wy + (size_t)(kc * 32 + kk) * DD + c4 * 4);
        }
        float* hd = Hsm + buf * (64 * 40);
        {
            int bb = tid >> 3, k4 = tid & 7;  // 512 = 64*8
            cp16(hd + bb * 40 + k4 * 4,
                 g_hs + ((size_t)t * BB + bb) * HH + kc * 32 + k4 * 4);
        }
    };

    prefetch(0, 0);
    cp_commit();

    for (int kc = 0; kc < 16; kc++) {
        int buf = kc & 1;
        if (kc < 15) prefetch(kc + 1, buf ^ 1);
        cp_commit();
        cp_wait<1>();
        __syncthreads();

        const float4* Wb4 = (const float4*)(Wsm + buf * (32 * 256));
        const float*  Hb  = Hsm + buf * (64 * 40);
#pragma unroll
        for (int kk4 = 0; kk4 < 8; kk4++) {
            float4 xq[4];
#pragma unroll
            for (int j = 0; j < 4; j++)
                xq[j] = *(const float4*)(Hb + (tb * 4 + j) * 40 + kk4 * 4);
#pragma unroll
            for (int q = 0; q < 4; q++) {
                int kk = kk4 * 4 + q;
                ulonglong2 w0 = *(const ulonglong2*)(Wb4 + kk * 64 + tc);
                ulonglong2 w1 = *(const ulonglong2*)(Wb4 + kk * 64 + 32 + tc);
#pragma unroll
                for (int j = 0; j < 4; j++) {
                    float xs = ((const float*)&xq[j])[q];
                    unsigned long long hj = bcast2(xs);
                    fma2(A[j][0], hj, w0.x);
                    fma2(A[j][1], hj, w0.y);
                    fma2(A[j][2], hj, w1.x);
                    fma2(A[j][3], hj, w1.y);
                }
            }
        }
        __syncthreads();
    }

    // epilogue: d0 = tc*4 (pairs A[j][0],A[j][1]); d1 = 128 + tc*4 (A[j][2],A[j][3])
#pragma unroll
    for (int j = 0; j < 4; j++) {
#pragma unroll
        for (int i2 = 0; i2 < 2; i2++) {
            int d = i2 * 128 + tc * 4;
            float2 v0 = unpack2(A[j][i2 * 2 + 0]);
            float2 v1 = unpack2(A[j][i2 * 2 + 1]);
            float4 v = make_float4(v0.x + by[d + 0], v0.y + by[d + 1],
                                   v1.x + by[d + 2], v1.y + by[d + 3]);
            *(float4*)(y + (((size_t)(tb * 4 + j)) * TT + t) * DD + d) = v;
        }
    }
}

// =====================================================================
extern "C" void kernel_launch(void* const* d_in, const int* in_sizes, int n_in,
                              void* d_out, int out_size)
{
    (void)in_sizes; (void)n_in; (void)out_size;
    const float* x  = (const float*)d_in[0];
    const float* h0 = (const float*)d_in[1];
    const float* c0 = (const float*)d_in[2];
    const float* Wj = (const float*)d_in[3];
    const float* Wi = (const float*)d_in[4];
    const float* Wf = (const float*)d_in[5];
    const float* Wo = (const float*)d_in[6];
    const float* Uj = (const float*)d_in[7];
    const float* Ui = (const float*)d_in[8];
    const float* Uf = (const float*)d_in[9];
    const float* Uo = (const float*)d_in[10];
    const float* bj = (const float*)d_in[11];
    const float* bi = (const float*)d_in[12];
    const float* bf = (const float*)d_in[13];
    const float* bo = (const float*)d_in[14];
    const float* Wy = (const float*)d_in[15];
    const float* by = (const float*)d_in[16];
    float* out = (float*)d_out;

    const size_t smem_proj = (size_t)(2 * 32 * 128 + 2 * 64 * 40) * 4;  // 53,248
    const size_t smem_rec  = (size_t)(64 * 512 + 512 * 16) * 4;         // 163,840
    const size_t smem_y    = (size_t)(2 * 32 * 256 + 2 * 64 * 40) * 4;  // 86,016

    cudaFuncSetAttribute(proj_kernel,  cudaFuncAttributeMaxDynamicSharedMemorySize, (int)smem_proj);
    cudaFuncSetAttribute(recur_kernel, cudaFuncAttributeMaxDynamicSharedMemorySize, (int)smem_rec);
    cudaFuncSetAttribute(ygemm_kernel, cudaFuncAttributeMaxDynamicSharedMemorySize, (int)smem_y);

    proj_kernel<<<dim3(16, TT), 256, smem_proj>>>(x, Wj, Wi, Wf, Wo, bj, bi, bf, bo);
    recur_kernel<<<RBLOCKS, 256, smem_rec>>>(h0, c0, Uj, Ui, Uf, Uo, out);
    ygemm_kernel<<<TT, 512, smem_y>>>(Wy, by, out);
}

// round 4
// speedup vs baseline: 1.5596x; 1.1590x over previous
#include <cuda_runtime.h>
#include <cstdint>
#include <cstddef>

#define BB 64
#define TT 2048
#define DD 256
#define HH 512
#define GCN 2048   /* 4*HH gate columns: [j|i|f|o] */
#define RBLOCKS 128

typedef unsigned long long ull;

// ---------------- scratch (device globals: allocation-free rule) ----------------
__device__ float g_xproj[(size_t)TT * GCN * BB];   // [t][gc][b]  (1 GiB)
__device__ float g_hs[(size_t)TT * BB * HH];       // [t][b][h]   (256 MiB)
__device__ unsigned g_bar_gen;
__device__ unsigned g_bar_cnt;

__device__ __forceinline__ float fsigmoid_(float x) {
    return 1.0f / (1.0f + __expf(-x));
}
__device__ __forceinline__ float ftanh_(float x) {
    float e = __expf(2.0f * x);
    return 1.0f - 2.0f / (e + 1.0f);
}

// ---- packed f32x2 helpers (FFMA2 path: only reachable via PTX) ----
__device__ __forceinline__ ull bcast2(float v) {
    ull r;
    asm("mov.b64 %0, {%1, %1};" : "=l"(r) : "r"(__float_as_uint(v)));
    return r;
}
__device__ __forceinline__ void fma2(ull& d, ull a, ull b) {
    asm("fma.rn.f32x2 %0, %1, %2, %0;" : "+l"(d) : "l"(a), "l"(b));
}
__device__ __forceinline__ void add2(ull& d, ull a) {
    asm("add.rn.f32x2 %0, %0, %1;" : "+l"(d) : "l"(a));
}
__device__ __forceinline__ float2 unpack2(ull v) {
    unsigned lo, hi;
    asm("mov.b64 {%0, %1}, %2;" : "=r"(lo), "=r"(hi) : "l"(v));
    return make_float2(__uint_as_float(lo), __uint_as_float(hi));
}

// ---- cp.async helpers ----
__device__ __forceinline__ void cp16(void* dst_smem, const void* src_gmem) {
    unsigned d = (unsigned)__cvta_generic_to_shared(dst_smem);
    asm volatile("cp.async.cg.shared.global [%0], [%1], 16;\n" :: "r"(d), "l"(src_gmem));
}
__device__ __forceinline__ void cp_commit() {
    asm volatile("cp.async.commit_group;\n");
}
template <int N> __device__ __forceinline__ void cp_wait() {
    asm volatile("cp.async.wait_group %0;\n" :: "n"(N));
}

// =====================================================================
// Kernel 1: input projections (double-buffered SGEMM, f32x2 math)
// =====================================================================
__global__ void __launch_bounds__(256) proj_kernel(
    const float* __restrict__ x,
    const float* __restrict__ Wj, const float* __restrict__ Wi,
    const float* __restrict__ Wf, const float* __restrict__ Wo,
    const float* __restrict__ bj, const float* __restrict__ bi,
    const float* __restrict__ bf, const float* __restrict__ bo)
{
    extern __shared__ float sm[];
    float* Wsm = sm;                 // [2][32 kk][128 gc]
    float* Xsm = sm + 2 * 32 * 128;  // [2][64 b][40]

    const int t   = blockIdx.y;
    const int gc0 = blockIdx.x * 128;
    const int g   = gc0 >> 9;
    const int hq0 = gc0 & 511;
    const float* W  = (g == 0) ? Wj : (g == 1) ? Wi : (g == 2) ? Wf : Wo;
    const float* bv = (g == 0) ? bj : (g == 1) ? bi : (g == 2) ? bf : bo;
    const int tid = threadIdx.x;
    const int tb = tid >> 4;
    const int tc = tid & 15;

    ull A[4][4];
#pragma unroll
    for (int j = 0; j < 4; j++)
#pragma unroll
        for (int p = 0; p < 4; p++) A[j][p] = 0ull;

    auto prefetch = [&](int kc, int buf) {
        const float* Wp = W + (size_t)(kc * 32) * HH + hq0;
        float* wd = Wsm + buf * (32 * 128);
#pragma unroll
        for (int r = 0; r < 4; r++) {
            int idx = r * 256 + tid;
            int kk = idx >> 5, c4 = idx & 31;
            cp16(wd + kk * 128 + c4 * 4, Wp + (size_t)kk * HH + c4 * 4);
        }
        float* xd = Xsm + buf * (64 * 40);
#pragma unroll
        for (int r = 0; r < 2; r++) {
            int idx = r * 256 + tid;
            int bb = idx >> 3, k4 = idx & 7;
            cp16(xd + bb * 40 + k4 * 4,
                 x + ((size_t)bb * TT + t) * DD + kc * 32 + k4 * 4);
        }
    };

    prefetch(0, 0);
    cp_commit();

    for (int kc = 0; kc < 8; kc++) {
        int buf = kc & 1;
        if (kc < 7) prefetch(kc + 1, buf ^ 1);
        cp_commit();
        cp_wait<1>();
        __syncthreads();

        const float4* Wb4 = (const float4*)(Wsm + buf * (32 * 128));
        const float*  Xb  = Xsm + buf * (64 * 40);
#pragma unroll
        for (int kk4 = 0; kk4 < 8; kk4++) {
            float4 xq[4];
#pragma unroll
            for (int j = 0; j < 4; j++)
                xq[j] = *(const float4*)(Xb + (tb * 4 + j) * 40 + kk4 * 4);
#pragma unroll
            for (int q = 0; q < 4; q++) {
                int kk = kk4 * 4 + q;
                ulonglong2 w0 = *(const ulonglong2*)(Wb4 + kk * 32 + tc);
                ulonglong2 w1 = *(const ulonglong2*)(Wb4 + kk * 32 + 16 + tc);
#pragma unroll
                for (int j = 0; j < 4; j++) {
                    float xs = ((const float*)&xq[j])[q];
                    ull hj = bcast2(xs);
                    fma2(A[j][0], hj, w0.x);
                    fma2(A[j][1], hj, w0.y);
                    fma2(A[j][2], hj, w1.x);
                    fma2(A[j][3], hj, w1.y);
                }
            }
        }
        __syncthreads();
    }

    float acc[4][8];
#pragma unroll
    for (int j = 0; j < 4; j++)
#pragma unroll
        for (int p = 0; p < 4; p++) {
            float2 v = unpack2(A[j][p]);
            acc[j][p * 2 + 0] = v.x;
            acc[j][p * 2 + 1] = v.y;
        }
#pragma unroll
    for (int i4 = 0; i4 < 2; i4++) {
#pragma unroll
        for (int q = 0; q < 4; q++) {
            int c = i4 * 64 + tc * 4 + q;
            float bb = bv[hq0 + c];
            float4 v = make_float4(acc[0][i4 * 4 + q] + bb, acc[1][i4 * 4 + q] + bb,
                                   acc[2][i4 * 4 + q] + bb, acc[3][i4 * 4 + q] + bb);
            *(float4*)(g_xproj + ((size_t)t * GCN + gc0 + c) * BB + tb * 4) = v;
        }
    }
}

// =====================================================================
// Kernel 2: persistent recurrence. 128 blocks x 256 threads.
// NEW warp map: lane = (l<<3)|bq, b = wid*8+bq -> 4 lanes share each h
// address (h LDS = 1 wavefront), U in padded [k4][l][g][4hk] layout
// (conflict-free, pairs align with raw float4 reg pairs: zero movs).
// cp.async staging; spin barrier without nanosleep.
// =====================================================================
__global__ void __launch_bounds__(256) recur_kernel(
    const float* __restrict__ h0in, const float* __restrict__ c0in,
    const float* __restrict__ Uj, const float* __restrict__ Ui,
    const float* __restrict__ Uf, const float* __restrict__ Uo,
    float* __restrict__ dout)
{
    extern __shared__ float sm[];
    float* h_smf = sm;               // [64 b][512 k], xor-swizzled float4
    float* U_sm  = sm + 64 * 512;    // [128 k4][4 l][20]: 16 used (4g x 4hk) + 4 pad

    const int tid = threadIdx.x;
    const int hq_base = blockIdx.x * 4;

    // U fill: U_sm[k4*80 + l*20 + g*4 + i] = U_g[(k4*4+i)][hq_base+l]
    for (int idx = tid; idx < 128 * 80; idx += 256) {
        int k4 = idx / 80;
        int r  = idx - k4 * 80;
        int l  = r / 20;
        int s  = r - l * 20;
        float v = 0.0f;
        if (s < 16) {
            int g = s >> 2, i = s & 3;
            const float* Up = (g == 0) ? Uj : (g == 1) ? Ui : (g == 2) ? Uf : Uo;
            v = Up[(size_t)(k4 * 4 + i) * HH + hq_base + l];
        }
        U_sm[idx] = v;
    }
    __syncthreads();

    const int wid  = tid >> 5;
    const int lane = tid & 31;
    const int l    = lane >> 3;          // hq lane 0..3
    const int b    = wid * 8 + (lane & 7);
    const int xm   = b & 7;
    const int hq   = hq_base + l;

    float4* h4 = (float4*)h_smf;
    const ulonglong2* h2 = (const ulonglong2*)h_smf;
    const float* Ub = U_sm + l * 20;

    float c = c0in[(size_t)b * HH + hq];
    float hval = 0.0f;

    for (int t = 0; t < TT; t++) {
        // xproj loads first: latency hidden under staging + compute
        const float* xp = g_xproj + (size_t)t * GCN * BB;
        float pj = xp[((size_t)0 * HH + hq) * BB + b];
        float pi = xp[((size_t)1 * HH + hq) * BB + b];
        float pf = xp[((size_t)2 * HH + hq) * BB + b];
        float po = xp[((size_t)3 * HH + hq) * BB + b];

        // stage h_{t-1} via cp.async into swizzled smem
        const float4* src = (t == 0) ? (const float4*)h0in
                                     : (const float4*)(g_hs + (size_t)(t - 1) * BB * HH);
#pragma unroll
        for (int r = 0; r < 32; r++) {
            int idx = r * 256 + tid;
            int bb = idx >> 7, k4 = idx & 127;
            cp16(&h4[bb * 128 + (k4 ^ (bb & 7))], &src[idx]);
        }
        cp_commit();
        cp_wait<0>();
        __syncthreads();

        // 8 fma2 chains (2 per gate: even/odd hk partials), no packing movs
        ull A00 = 0, A01 = 0, A10 = 0, A11 = 0;
        ull A20 = 0, A21 = 0, A30 = 0, A31 = 0;
#pragma unroll 4
        for (int k4 = 0; k4 < 128; k4++) {
            ulonglong2 hp = h2[b * 128 + (k4 ^ xm)];
            const float* Uc = Ub + k4 * 80;
            ulonglong2 u0 = *(const ulonglong2*)(Uc + 0);
            ulonglong2 u1 = *(const ulonglong2*)(Uc + 4);
            ulonglong2 u2 = *(const ulonglong2*)(Uc + 8);
            ulonglong2 u3 = *(const ulonglong2*)(Uc + 12);
            fma2(A00, hp.x, u0.x); fma2(A01, hp.y, u0.y);
            fma2(A10, hp.x, u1.x); fma2(A11, hp.y, u1.y);
            fma2(A20, hp.x, u2.x); fma2(A21, hp.y, u2.y);
            fma2(A30, hp.x, u3.x); fma2(A31, hp.y, u3.y);
        }
        add2(A00, A01); add2(A10, A11); add2(A20, A21); add2(A30, A31);
        float2 vj = unpack2(A00), vi = unpack2(A10);
        float2 vf = unpack2(A20), vo = unpack2(A30);

        // gates: j,i,o sigmoid; f tanh (module default quirk)
        float aj = fsigmoid_(pj + vj.x + vj.y);
        float ai = fsigmoid_(pi + vi.x + vi.y);
        float af = ftanh_(pf + vf.x + vf.y);
        float ao = fsigmoid_(po + vo.x + vo.y);
        c = fmaf(af, c, ai * aj);
        hval = ao * ftanh_(c);
        g_hs[((size_t)t * BB + b) * HH + hq] = hval;

        // grid barrier: tight spin, no nanosleep
        __syncthreads();
        if (tid == 0) {
            __threadfence();
            unsigned myg = *(volatile unsigned*)&g_bar_gen;
            if (atomicAdd(&g_bar_cnt, 1u) == RBLOCKS - 1) {
                g_bar_cnt = 0;
                __threadfence();
                *(volatile unsigned*)&g_bar_gen = myg + 1u;
            } else {
                while (*(volatile unsigned*)&g_bar_gen == myg) { }
            }
            __threadfence();
        }
        __syncthreads();
    }

    {
        size_t OH = (size_t)BB * TT * DD;
        dout[OH + (size_t)b * HH + hq] = hval;
        dout[OH + (size_t)BB * HH + (size_t)b * HH + hq] = c;
    }
}

// =====================================================================
// Kernel 3: y[b][t][d] = sum_h hs[t][b][h] * Wy[h][d] + by[d]
// =====================================================================
__global__ void __launch_bounds__(512) ygemm_kernel(
    const float* __restrict__ Wy, const float* __restrict__ by,
    float* __restrict__ y)
{
    extern __shared__ float sm[];
    float* Wsm = sm;                 // [2][32 kk][256 d]
    float* Hsm = sm + 2 * 32 * 256;  // [2][64 b][40]

    const int t = blockIdx.x;
    const int tid = threadIdx.x;
    const int tb = tid >> 5;
    const int tc = tid & 31;

    ull A[4][4];
#pragma unroll
    for (int j = 0; j < 4; j++)
#pragma unroll
        for (int p = 0; p < 4; p++) A[j][p] = 0ull;

    auto prefetch = [&](int kc, int buf) {
        float* wd = Wsm + buf * (32 * 256);
#pragma unroll
        for (int r = 0; r < 4; r++) {
            int idx = r * 512 + tid;
            int kk = idx >> 6, c4 = idx & 63;
            cp16(wd + kk * 256 + c4 * 4,
                 Wy + (size_t)(kc * 32 + kk) * DD + c4 * 4);
        }
        float* hd = Hsm + buf * (64 * 40);
        {
            int bb = tid >> 3, k4 = tid & 7;
            cp16(hd + bb * 40 + k4 * 4,
                 g_hs + ((size_t)t * BB + bb) * HH + kc * 32 + k4 * 4);
        }
    };

    prefetch(0, 0);
    cp_commit();

    for (int kc = 0; kc < 16; kc++) {
        int buf = kc & 1;
        if (kc < 15) prefetch(kc + 1, buf ^ 1);
        cp_commit();
        cp_wait<1>();
        __syncthreads();

        const float4* Wb4 = (const float4*)(Wsm + buf * (32 * 256));
        const float*  Hb  = Hsm + buf * (64 * 40);
#pragma unroll
        for (int kk4 = 0; kk4 < 8; kk4++) {
            float4 xq[4];
#pragma unroll
            for (int j = 0; j < 4; j++)
                xq[j] = *(const float4*)(Hb + (tb * 4 + j) * 40 + kk4 * 4);
#pragma unroll
            for (int q = 0; q < 4; q++) {
                int kk = kk4 * 4 + q;
                ulonglong2 w0 = *(const ulonglong2*)(Wb4 + kk * 64 + tc);
                ulonglong2 w1 = *(const ulonglong2*)(Wb4 + kk * 64 + 32 + tc);
#pragma unroll
                for (int j = 0; j < 4; j++) {
                    float xs = ((const float*)&xq[j])[q];
                    ull hj = bcast2(xs);
                    fma2(A[j][0], hj, w0.x);
                    fma2(A[j][1], hj, w0.y);
                    fma2(A[j][2], hj, w1.x);
                    fma2(A[j][3], hj, w1.y);
                }
            }
        }
        __syncthreads();
    }

#pragma unroll
    for (int j = 0; j < 4; j++) {
#pragma unroll
        for (int i2 = 0; i2 < 2; i2++) {
            int d = i2 * 128 + tc * 4;
            float2 v0 = unpack2(A[j][i2 * 2 + 0]);
            float2 v1 = unpack2(A[j][i2 * 2 + 1]);
            float4 v = make_float4(v0.x + by[d + 0], v0.y + by[d + 1],
                                   v1.x + by[d + 2], v1.y + by[d + 3]);
            *(float4*)(y + (((size_t)(tb * 4 + j)) * TT + t) * DD + d) = v;
        }
    }
}

// =====================================================================
extern "C" void kernel_launch(void* const* d_in, const int* in_sizes, int n_in,
                              void* d_out, int out_size)
{
    (void)in_sizes; (void)n_in; (void)out_size;
    const float* x  = (const float*)d_in[0];
    const float* h0 = (const float*)d_in[1];
    const float* c0 = (const float*)d_in[2];
    const float* Wj = (const float*)d_in[3];
    const float* Wi = (const float*)d_in[4];
    const float* Wf = (const float*)d_in[5];
    const float* Wo = (const float*)d_in[6];
    const float* Uj = (const float*)d_in[7];
    const float* Ui = (const float*)d_in[8];
    const float* Uf = (const float*)d_in[9];
    const float* Uo = (const float*)d_in[10];
    const float* bj = (const float*)d_in[11];
    const float* bi = (const float*)d_in[12];
    const float* bf = (const float*)d_in[13];
    const float* bo = (const float*)d_in[14];
    const float* Wy = (const float*)d_in[15];
    const float* by = (const float*)d_in[16];
    float* out = (float*)d_out;

    const size_t smem_proj = (size_t)(2 * 32 * 128 + 2 * 64 * 40) * 4;  // 53,248
    const size_t smem_rec  = (size_t)(64 * 512 + 128 * 80) * 4;         // 172,032
    const size_t smem_y    = (size_t)(2 * 32 * 256 + 2 * 64 * 40) * 4;  // 86,016

    cudaFuncSetAttribute(proj_kernel,  cudaFuncAttributeMaxDynamicSharedMemorySize, (int)smem_proj);
    cudaFuncSetAttribute(recur_kernel, cudaFuncAttributeMaxDynamicSharedMemorySize, (int)smem_rec);
    cudaFuncSetAttribute(ygemm_kernel, cudaFuncAttributeMaxDynamicSharedMemorySize, (int)smem_y);

    proj_kernel<<<dim3(16, TT), 256, smem_proj>>>(x, Wj, Wi, Wf, Wo, bj, bi, bf, bo);
    recur_kernel<<<RBLOCKS, 256, smem_rec>>>(h0, c0, Uj, Ui, Uf, Uo, out);
    ygemm_kernel<<<TT, 512, smem_y>>>(Wy, by, out);
}